// round 9
// baseline (speedup 1.0000x reference)
#include <cuda_runtime.h>
#include <cstdint>
#include <cstddef>

// ---------------------------------------------------------------------------
// BlocDiagLinear: out[b, n*128+r] = sum_c x[b, n*128+c] * blocks[n, r, c]
// 64 GEMMs (M=4096, N=128, K=128) fp32 -> mma.sync.m16n8k8.tf32, fp32 accum.
//
// R9: grid (64, 32), CTA tile 128x128x128, 8 warps (4M x 2N), warp 32x64.
//  - K in 8 chunks of 16; cp.async 6-stage ring (A 8KB + B 8KB per stage).
//  - XOR swizzle on 16B atoms within 64B rows: c ^= (row>>1)&3.
//  - ldmatrix.x4 fragment loads; BOTH A and B rna-rounded to tf32 in-register
//    (no pre-kernel, no scratch). Same rounding math as R6/R8.
// ---------------------------------------------------------------------------

static constexpr int THREADS = 256;
static constexpr int STAGE_BYTES = 16384;            // A 8KB + B 8KB
static constexpr int NSTAGE = 6;
static constexpr int SMEM_BYTES  = NSTAGE * STAGE_BYTES;  // 98304 -> 2 CTAs/SM

__device__ __forceinline__ uint32_t smem_u32(const void* p) {
    uint32_t a;
    asm("{ .reg .u64 t; cvta.to.shared.u64 t, %1; cvt.u32.u64 %0, t; }"
        : "=r"(a) : "l"(p));
    return a;
}

__device__ __forceinline__ uint32_t f2tf32(float f) {
    uint32_t r;
    asm("cvt.rna.tf32.f32 %0, %1;" : "=r"(r) : "f"(f));
    return r;
}

// Issue one K=16 chunk (A: x tile, B: blocks) into stage buffer `sbase`.
__device__ __forceinline__ void issue_stage(uint32_t sbase,
                                            const float* __restrict__ xg,
                                            const float* __restrict__ bg,
                                            int s)
{
    #pragma unroll
    for (int it = 0; it < 2; it++) {
        const int j   = threadIdx.x + it * 256;   // 0..511 int4 atoms
        const int row = j >> 2;                   // 0..127
        const int c   = j & 3;                    // 16B atom within 64B row
        const uint32_t sw = (uint32_t)((c ^ ((row >> 1) & 3)) << 4);
        const uint32_t dA = sbase + row * 64 + sw;
        const float* sA = xg + (size_t)row * 8192 + s * 16 + c * 4;
        asm volatile("cp.async.cg.shared.global [%0], [%1], 16;"
                     :: "r"(dA), "l"(sA));
        const uint32_t dB = sbase + 8192 + row * 64 + sw;
        const float* sB = bg + row * 128 + s * 16 + c * 4;
        asm volatile("cp.async.cg.shared.global [%0], [%1], 16;"
                     :: "r"(dB), "l"(sB));
    }
    asm volatile("cp.async.commit_group;" ::: "memory");
}

// Compute one K=16 chunk (2 k-steps of m16n8k8).
__device__ __forceinline__ void compute_stage(uint32_t abase, uint32_t bbase,
                                              int mrow, int ncol, int lane,
                                              float acc[2][8][4])
{
    const int t4 = lane >> 3;     // tile index within ldmatrix.x4
    const int tr = lane & 7;      // row within tile

    #pragma unroll
    for (int kkl = 0; kkl < 2; kkl++) {
        // ---- A fragments: 2 x ldmatrix.x4, then rna-round to tf32
        uint32_t a[2][4];
        #pragma unroll
        for (int i = 0; i < 2; i++) {
            const int r = mrow + 16 * i + ((t4 & 1) << 3) + tr;
            const int c = 2 * kkl + (t4 >> 1);
            const uint32_t addr = abase + r * 64
                                + ((uint32_t)(c ^ ((r >> 1) & 3)) << 4);
            asm volatile(
                "ldmatrix.sync.aligned.m8n8.x4.shared.b16 {%0,%1,%2,%3}, [%4];"
                : "=r"(a[i][0]), "=r"(a[i][1]), "=r"(a[i][2]), "=r"(a[i][3])
                : "r"(addr));
        }
        #pragma unroll
        for (int i = 0; i < 2; i++)
            #pragma unroll
            for (int q = 0; q < 4; q++)
                a[i][q] = f2tf32(__uint_as_float(a[i][q]));

        // ---- B fragments: 4 x ldmatrix.x4 (jj pairs), rna-round to tf32
        uint32_t b[8][2];
        #pragma unroll
        for (int p = 0; p < 4; p++) {
            const int rn = ncol + (2 * p + (t4 >> 1)) * 8 + tr;
            const int c  = 2 * kkl + (t4 & 1);
            const uint32_t addr = bbase + rn * 64
                                + ((uint32_t)(c ^ ((rn >> 1) & 3)) << 4);
            asm volatile(
                "ldmatrix.sync.aligned.m8n8.x4.shared.b16 {%0,%1,%2,%3}, [%4];"
                : "=r"(b[2 * p][0]), "=r"(b[2 * p][1]),
                  "=r"(b[2 * p + 1][0]), "=r"(b[2 * p + 1][1])
                : "r"(addr));
        }
        #pragma unroll
        for (int jj = 0; jj < 8; jj++) {
            b[jj][0] = f2tf32(__uint_as_float(b[jj][0]));
            b[jj][1] = f2tf32(__uint_as_float(b[jj][1]));
        }

        // ---- 16 mma
        #pragma unroll
        for (int jj = 0; jj < 8; jj++)
            #pragma unroll
            for (int i = 0; i < 2; i++) {
                asm volatile(
                    "mma.sync.aligned.m16n8k8.row.col.f32.tf32.tf32.f32 "
                    "{%0,%1,%2,%3}, {%4,%5,%6,%7}, {%8,%9}, {%0,%1,%2,%3};"
                    : "+f"(acc[i][jj][0]), "+f"(acc[i][jj][1]),
                      "+f"(acc[i][jj][2]), "+f"(acc[i][jj][3])
                    : "r"(a[i][0]), "r"(a[i][1]), "r"(a[i][2]), "r"(a[i][3]),
                      "r"(b[jj][0]), "r"(b[jj][1]));
            }
    }
}

__global__ void __launch_bounds__(THREADS, 2)
bdl_mma_kernel(const float* __restrict__ x,
               const float* __restrict__ blocks,
               float* __restrict__ out)
{
    extern __shared__ char smem[];
    const uint32_t sb = smem_u32(smem);

    const int tid  = threadIdx.x;
    const int wid  = tid >> 5;
    const int lane = tid & 31;
    const int g    = lane >> 2;
    const int tig  = lane & 3;

    const int n  = blockIdx.x;
    const int m0 = blockIdx.y * 128;

    const int mrow = (wid >> 1) * 32;
    const int ncol = (wid & 1) * 64;

    const float* xg = x + (size_t)m0 * 8192 + n * 128;
    const float* bg = blocks + (size_t)n * 16384;

    float acc[2][8][4];
    #pragma unroll
    for (int i = 0; i < 2; i++)
        #pragma unroll
        for (int j = 0; j < 8; j++)
            #pragma unroll
            for (int v = 0; v < 4; v++)
                acc[i][j][v] = 0.0f;

    // ---- prologue: fill ring with chunks 0..5 ----
    #pragma unroll
    for (int s = 0; s < NSTAGE; s++)
        issue_stage(sb + s * STAGE_BYTES, xg, bg, s);

    // ---- mainloop over 8 chunks; chunk c lives in buffer c % 6 ----
    // Before computing chunk c: pending groups must be <= issued - (c+1).
    #define BDL_STEP(c, wn, do_issue)                                        \
    {                                                                        \
        asm volatile("cp.async.wait_group %0;" :: "n"(wn) : "memory");       \
        __syncthreads();                                                     \
        const uint32_t buf = sb + ((c) % NSTAGE) * STAGE_BYTES;              \
        compute_stage(buf, buf + 8192, mrow, ncol, lane, acc);               \
        if (do_issue) {                                                      \
            __syncthreads();                                                 \
            issue_stage(buf, xg, bg, (c) + NSTAGE);                          \
        }                                                                    \
    }

    BDL_STEP(0, 5, true);   // issued 6 -> need chunk0 done: pending<=5; then issue 6
    BDL_STEP(1, 5, true);   // issued 7 -> chunk1 done: pending<=5; issue 7
    BDL_STEP(2, 5, false);  // issued 8 -> chunk2 done: pending<=5
    BDL_STEP(3, 4, false);
    BDL_STEP(4, 3, false);
    BDL_STEP(5, 2, false);
    BDL_STEP(6, 1, false);
    BDL_STEP(7, 0, false);
    #undef BDL_STEP

    // ---- epilogue: float2 stores ----
    float* obase = out + (size_t)m0 * 8192 + n * 128;
    #pragma unroll
    for (int i = 0; i < 2; i++) {
        const int r0 = mrow + 16 * i + g;
        #pragma unroll
        for (int jj = 0; jj < 8; jj++) {
            const int c = ncol + 8 * jj + 2 * tig;
            *reinterpret_cast<float2*>(obase + (size_t)r0 * 8192 + c) =
                make_float2(acc[i][jj][0], acc[i][jj][1]);
            *reinterpret_cast<float2*>(obase + (size_t)(r0 + 8) * 8192 + c) =
                make_float2(acc[i][jj][2], acc[i][jj][3]);
        }
    }
}

extern "C" void kernel_launch(void* const* d_in, const int* in_sizes, int n_in,
                              void* d_out, int out_size)
{
    (void)in_sizes; (void)n_in; (void)out_size;
    const float* x      = (const float*)d_in[0];   // [4096, 8192]
    const float* blocks = (const float*)d_in[1];   // [64, 128, 128]
    float* out          = (float*)d_out;           // [4096, 8192]

    cudaFuncSetAttribute(bdl_mma_kernel,
                         cudaFuncAttributeMaxDynamicSharedMemorySize, SMEM_BYTES);
    dim3 grid(64, 32, 1);
    bdl_mma_kernel<<<grid, THREADS, SMEM_BYTES>>>(x, blocks, out);
}

// round 10
// speedup vs baseline: 1.1651x; 1.1651x over previous
#include <cuda_runtime.h>
#include <cstdint>
#include <cstddef>

// ---------------------------------------------------------------------------
// BlocDiagLinear: out[b, n*128+r] = sum_c x[b, n*128+c] * blocks[n, r, c]
// 64 GEMMs (M=4096, N=128, K=128) fp32 -> mma.sync.m16n8k8.tf32, fp32 accum.
//
// R10 = R8 structure (best measured: 56.8us main kernel):
//   grid (64, 32), CTA tile 128x128x128, 8 warps (4M x 2N), warp 32x64.
//   K in 4 chunks of 32; cp.async 3-stage ring (A 16KB + B 16KB per stage).
//   XOR-swizzled smem (16B atom: c ^= row&7 within 128B rows), ldmatrix.x4.
// Changes vs R8: NO pre-kernel, NO in-register cvt. mma.tf32 hardware
// truncates fp32 operands to tf32 for free (low mantissa bits ignored).
// Error: truncation is value-proportional -> ~4.8e-4 systematic rel err.
// ---------------------------------------------------------------------------

static constexpr int THREADS = 256;
static constexpr int STAGE_BYTES = 32768;            // A 16KB + B 16KB
static constexpr int SMEM_BYTES  = 3 * STAGE_BYTES;  // 98304 -> 2 CTAs/SM

__device__ __forceinline__ uint32_t smem_u32(const void* p) {
    uint32_t a;
    asm("{ .reg .u64 t; cvta.to.shared.u64 t, %1; cvt.u32.u64 %0, t; }"
        : "=r"(a) : "l"(p));
    return a;
}

// Issue one K=32 chunk (A: x tile, B: blocks[n]) via cp.async.
__device__ __forceinline__ void issue_stage(uint32_t sbase,
                                            const float* __restrict__ xg,
                                            const float* __restrict__ bg,
                                            int s)
{
    #pragma unroll
    for (int it = 0; it < 4; it++) {
        const int j   = threadIdx.x + it * 256;   // 0..1023 int4 atoms
        const int row = j >> 3;                   // 0..127
        const int c   = j & 7;                    // 16B atom within 128B row
        const uint32_t sw = (uint32_t)((c ^ (row & 7)) << 4);
        const uint32_t dA = sbase + row * 128 + sw;
        const float* sA = xg + (size_t)row * 8192 + s * 32 + c * 4;
        asm volatile("cp.async.cg.shared.global [%0], [%1], 16;"
                     :: "r"(dA), "l"(sA));
        const uint32_t dB = sbase + 16384 + row * 128 + sw;
        const float* sB = bg + row * 128 + s * 32 + c * 4;
        asm volatile("cp.async.cg.shared.global [%0], [%1], 16;"
                     :: "r"(dB), "l"(sB));
    }
    asm volatile("cp.async.commit_group;" ::: "memory");
}

// Compute one K=32 chunk (4 k-steps of m16n8k8). Raw fp32 fragments feed the
// tf32 mma directly; HW truncation handles the tf32 conversion.
__device__ __forceinline__ void compute_stage(uint32_t abase, uint32_t bbase,
                                              int mrow, int ncol, int lane,
                                              float acc[2][8][4])
{
    const int t4 = lane >> 3;     // tile index within ldmatrix.x4
    const int tr = lane & 7;      // row within tile

    #pragma unroll
    for (int kk = 0; kk < 4; kk++) {
        // ---- A fragments: 2 x ldmatrix.x4 (rows mrow+16i, k cols 8*kk..+8)
        uint32_t a[2][4];
        #pragma unroll
        for (int i = 0; i < 2; i++) {
            const int r = mrow + 16 * i + ((t4 & 1) << 3) + tr;
            const int c = 2 * kk + (t4 >> 1);
            const uint32_t addr = abase + r * 128 + ((uint32_t)(c ^ (r & 7)) << 4);
            asm volatile(
                "ldmatrix.sync.aligned.m8n8.x4.shared.b16 {%0,%1,%2,%3}, [%4];"
                : "=r"(a[i][0]), "=r"(a[i][1]), "=r"(a[i][2]), "=r"(a[i][3])
                : "r"(addr));
        }

        // ---- B fragments: 4 x ldmatrix.x4 cover jj pairs {0,1},{2,3},{4,5},{6,7}
        uint32_t b[8][2];
        #pragma unroll
        for (int p = 0; p < 4; p++) {
            const int rn = ncol + (2 * p + (t4 >> 1)) * 8 + tr;
            const int c  = 2 * kk + (t4 & 1);
            const uint32_t addr = bbase + rn * 128 + ((uint32_t)(c ^ (rn & 7)) << 4);
            asm volatile(
                "ldmatrix.sync.aligned.m8n8.x4.shared.b16 {%0,%1,%2,%3}, [%4];"
                : "=r"(b[2 * p][0]), "=r"(b[2 * p][1]),
                  "=r"(b[2 * p + 1][0]), "=r"(b[2 * p + 1][1])
                : "r"(addr));
        }

        // ---- 16 mma per k-step
        #pragma unroll
        for (int jj = 0; jj < 8; jj++)
            #pragma unroll
            for (int i = 0; i < 2; i++) {
                asm volatile(
                    "mma.sync.aligned.m16n8k8.row.col.f32.tf32.tf32.f32 "
                    "{%0,%1,%2,%3}, {%4,%5,%6,%7}, {%8,%9}, {%0,%1,%2,%3};"
                    : "+f"(acc[i][jj][0]), "+f"(acc[i][jj][1]),
                      "+f"(acc[i][jj][2]), "+f"(acc[i][jj][3])
                    : "r"(a[i][0]), "r"(a[i][1]), "r"(a[i][2]), "r"(a[i][3]),
                      "r"(b[jj][0]), "r"(b[jj][1]));
            }
    }
}

__global__ void __launch_bounds__(THREADS, 2)
bdl_mma_kernel(const float* __restrict__ x,
               const float* __restrict__ blocks,
               float* __restrict__ out)
{
    extern __shared__ char smem[];
    const uint32_t sb = smem_u32(smem);

    const int tid  = threadIdx.x;
    const int wid  = tid >> 5;
    const int lane = tid & 31;
    const int g    = lane >> 2;
    const int tig  = lane & 3;

    const int n  = blockIdx.x;
    const int m0 = blockIdx.y * 128;

    const int mrow = (wid >> 1) * 32;
    const int ncol = (wid & 1) * 64;

    const float* xg = x + (size_t)m0 * 8192 + n * 128;
    const float* bg = blocks + (size_t)n * 16384;

    float acc[2][8][4];
    #pragma unroll
    for (int i = 0; i < 2; i++)
        #pragma unroll
        for (int j = 0; j < 8; j++)
            #pragma unroll
            for (int v = 0; v < 4; v++)
                acc[i][j][v] = 0.0f;

    // ---- prologue: fill ring with stages 0..2 ----
    issue_stage(sb + 0 * STAGE_BYTES, xg, bg, 0);
    issue_stage(sb + 1 * STAGE_BYTES, xg, bg, 1);
    issue_stage(sb + 2 * STAGE_BYTES, xg, bg, 2);

    // ---- stage 0 ----
    asm volatile("cp.async.wait_group 2;" ::: "memory");
    __syncthreads();
    compute_stage(sb + 0 * STAGE_BYTES, sb + 0 * STAGE_BYTES + 16384,
                  mrow, ncol, lane, acc);
    __syncthreads();                       // buf0 free before reuse
    issue_stage(sb + 0 * STAGE_BYTES, xg, bg, 3);

    // ---- stage 1 ----
    asm volatile("cp.async.wait_group 2;" ::: "memory");
    __syncthreads();
    compute_stage(sb + 1 * STAGE_BYTES, sb + 1 * STAGE_BYTES + 16384,
                  mrow, ncol, lane, acc);

    // ---- stage 2 ----
    asm volatile("cp.async.wait_group 1;" ::: "memory");
    __syncthreads();
    compute_stage(sb + 2 * STAGE_BYTES, sb + 2 * STAGE_BYTES + 16384,
                  mrow, ncol, lane, acc);

    // ---- stage 3 (in buf0) ----
    asm volatile("cp.async.wait_group 0;" ::: "memory");
    __syncthreads();
    compute_stage(sb + 0 * STAGE_BYTES, sb + 0 * STAGE_BYTES + 16384,
                  mrow, ncol, lane, acc);

    // ---- epilogue: float2 stores (each quad fills a full 32B sector) ----
    float* obase = out + (size_t)m0 * 8192 + n * 128;
    #pragma unroll
    for (int i = 0; i < 2; i++) {
        const int r0 = mrow + 16 * i + g;
        #pragma unroll
        for (int jj = 0; jj < 8; jj++) {
            const int c = ncol + 8 * jj + 2 * tig;
            *reinterpret_cast<float2*>(obase + (size_t)r0 * 8192 + c) =
                make_float2(acc[i][jj][0], acc[i][jj][1]);
            *reinterpret_cast<float2*>(obase + (size_t)(r0 + 8) * 8192 + c) =
                make_float2(acc[i][jj][2], acc[i][jj][3]);
        }
    }
}

extern "C" void kernel_launch(void* const* d_in, const int* in_sizes, int n_in,
                              void* d_out, int out_size)
{
    (void)in_sizes; (void)n_in; (void)out_size;
    const float* x      = (const float*)d_in[0];   // [4096, 8192]
    const float* blocks = (const float*)d_in[1];   // [64, 128, 128]
    float* out          = (float*)d_out;           // [4096, 8192]

    cudaFuncSetAttribute(bdl_mma_kernel,
                         cudaFuncAttributeMaxDynamicSharedMemorySize, SMEM_BYTES);
    dim3 grid(64, 32, 1);
    bdl_mma_kernel<<<grid, THREADS, SMEM_BYTES>>>(x, blocks, out);
}